// round 4
// baseline (speedup 1.0000x reference)
#include <cuda_runtime.h>
#include <math.h>

#define RP 32
#define RR 8
#define NB 8
#define NPT 32768
#define PI_F 3.14159265358979323846f

// ---------------- scratch (device globals; no allocation allowed) ----------------
__device__ float g_ft[NB * RR * RP * RP];     // (b, r, theta, phi)
__device__ float g_h1[NB * 32 * RP * RP];     // conv1 out
__device__ float g_h2[NB * 64 * RP * RP];     // conv2 out
__device__ float g_ftmax[NB * 64];
__device__ float g_Bvec[NB * 64];
__device__ float g_wq[RP];

// ---------------- f32x2 packed helpers ------------------------------------------
__device__ __forceinline__ unsigned long long ffma2(unsigned long long a,
                                                    unsigned long long b,
                                                    unsigned long long c) {
    unsigned long long d;
    asm("fma.rn.f32x2 %0, %1, %2, %3;" : "=l"(d) : "l"(a), "l"(b), "l"(c));
    return d;
}
__device__ __forceinline__ unsigned long long pack2(float lo, float hi) {
    unsigned long long d;
    asm("mov.b64 %0, {%1, %2};" : "=l"(d) : "f"(lo), "f"(hi));
    return d;
}
__device__ __forceinline__ void unpack2(unsigned long long v, float& lo, float& hi) {
    asm("mov.b64 {%0, %1}, %2;" : "=f"(lo), "=f"(hi) : "l"(v));
}

// ---------------- init: zero grid + quadrature weights --------------------------
__global__ void k_init() {
    int i = blockIdx.x * blockDim.x + threadIdx.x;   // 65536 threads
    g_ft[i] = 0.f;                                   // exactly covers 65536
    if (i < RP) {
        // Driscoll-Healy weights, bw = 16
        double jj = (double)i;
        double theta = M_PI * (2.0 * jj + 1.0) / 64.0;
        double s = 0.0;
        for (int k = 0; k < 16; k++)
            s += sin((2.0 * jj + 1.0) * (2.0 * k + 1.0) * M_PI / 64.0) / (2.0 * k + 1.0);
        g_wq[i] = (float)((2.0 / 16.0) * sin(theta) * s);
    }
}

// ---------------- scatter: gaussian splat of w into (b, r, t, p) grid ------------
__global__ void __launch_bounds__(256) k_scatter(const float* __restrict__ pts,
                          const float* __restrict__ scp, const float* __restrict__ sgp,
                          const float* __restrict__ Ap, const float* __restrict__ icp) {
    int i = blockIdx.x * blockDim.x + threadIdx.x;
    if (i >= NB * NPT) return;
    float scale = *scp, sigma = *sgp, A = *Ap, icc = *icp;
    float x = pts[i * 3 + 0], y = pts[i * 3 + 1], z = pts[i * 3 + 2];
    float r = fmaxf(sqrtf(x * x + y * y + z * z), 0.1f);
    float th = acosf(fminf(fmaxf(__fdividef(z, r), -1.f), 1.f));
    float ph = atan2f(y, x) + PI_F;
    float ct = th * (float)(RP / M_PI);
    float cp = ph * (float)(RP / (2.0 * M_PI));
    float cr = __fdividef(r, scale) * (float)RR;
    int it = min(max((int)floorf(ct), 0), RP - 1);
    int ip = min(max((int)floorf(cp), 0), RP - 1);
    int ir = min(max((int)floorf(cr), 0), RR - 1);
    float dt = ct - ((float)it + icc);
    float dp = cp - ((float)ip + icc);
    float dr = cr - ((float)ir + icc);
    float d2 = dt * dt + dp * dp + dr * dr;
    float w = A * __expf(-d2 * __fdividef(0.5f, sigma * sigma));
    int b = i >> 15;
    atomicAdd(&g_ft[((b * RR + ir) * RP + it) * RP + ip], w);
}

// ---------------- register-tiled 3x3 SAME conv + relu, 2-row tiles --------------
// block: 256 threads = (ocq: tid>>5 -> 8 quads of 4 oc, row: (tid>>4)&1, colq: tid&15 -> 2 cols)
// covers 32 oc x 2 rows x 32 cols. grid: (16 rowtiles, OCT/32, 8 b).
template<int ICP, int PHASES, int ICT, int OCT>
__global__ void __launch_bounds__(256) k_conv(const float* __restrict__ in,
                                              const float* __restrict__ W,
                                              const float* __restrict__ bias,
                                              float* __restrict__ outp) {
    __shared__ __align__(16) float s_in[ICP * 4 * 36];
    __shared__ __align__(16) float s_w[ICP * 9 * 32];
    const int tid = threadIdx.x;
    const int rt = blockIdx.x;
    const int ocg = blockIdx.y;
    const int b = blockIdx.z;
    const int r0 = rt * 2;
    const int colq = tid & 15;           // 16 quads of 2 cols
    const int row = (tid >> 4) & 1;      // 2 rows
    const int ocq = tid >> 5;            // 8 quads of 4 oc

    float acc[4][2];
    #pragma unroll
    for (int a = 0; a < 4; a++) {
        float bb = bias[ocg * 32 + ocq * 4 + a];
        acc[a][0] = bb; acc[a][1] = bb;
    }

    for (int ph = 0; ph < PHASES; ph++) {
        const int icb = ph * ICP;
        __syncthreads();
        for (int i = tid; i < ICP * 144; i += 256) {
            int ic = i / 144, rem = i % 144;
            int rr = rem / 36, cc = rem % 36;
            int X = r0 + rr - 1, Y = cc - 1;
            float v = 0.f;
            if (X >= 0 && X < 32 && Y >= 0 && Y < 32)
                v = in[((b * ICT + icb + ic) * 32 + X) * 32 + Y];
            s_in[i] = v;
        }
        for (int i = tid; i < ICP * 288; i += 256) {
            int ic = i / 288, rem = i % 288;
            int k9 = rem >> 5, oc = rem & 31;
            s_w[i] = W[(ocg * 32 + oc) * (ICT * 9) + (icb + ic) * 9 + k9];
        }
        __syncthreads();
        #pragma unroll 1
        for (int ic = 0; ic < ICP; ic++) {
            #pragma unroll
            for (int dy = 0; dy < 3; dy++) {
                const float* irow = &s_in[(ic * 4 + row + dy) * 36 + colq * 2];
                float2 f01 = *(const float2*)irow;
                float2 f23 = *(const float2*)(irow + 2);
                float f[4] = {f01.x, f01.y, f23.x, f23.y};
                const float* wr = &s_w[(ic * 3 + dy) * 96 + ocq * 4];
                float4 w0 = *(const float4*)(wr);
                float4 w1 = *(const float4*)(wr + 32);
                float4 w2 = *(const float4*)(wr + 64);
                #pragma unroll
                for (int k = 0; k < 2; k++) {
                    acc[0][k] += f[k] * w0.x;     acc[1][k] += f[k] * w0.y;
                    acc[2][k] += f[k] * w0.z;     acc[3][k] += f[k] * w0.w;
                    acc[0][k] += f[k + 1] * w1.x; acc[1][k] += f[k + 1] * w1.y;
                    acc[2][k] += f[k + 1] * w1.z; acc[3][k] += f[k + 1] * w1.w;
                    acc[0][k] += f[k + 2] * w2.x; acc[1][k] += f[k + 2] * w2.y;
                    acc[2][k] += f[k + 2] * w2.z; acc[3][k] += f[k + 2] * w2.w;
                }
            }
        }
    }
    #pragma unroll
    for (int a = 0; a < 4; a++) {
        float2 vv = make_float2(fmaxf(acc[a][0], 0.f), fmaxf(acc[a][1], 0.f));
        *(float2*)&outp[((b * OCT + ocg * 32 + ocq * 4 + a) * 32 + r0 + row) * 32 + colq * 2] = vv;
    }
}

// ---------------- ft_max[b,c] = (sum_xy h * wq[y]) * sum_g Wg[c,g] --------------
__global__ void k_ftmax(const float* __restrict__ Wg) {
    int bc = blockIdx.x;                  // 512
    int tid = threadIdx.x;                // 256
    const float* h = g_h2 + bc * 1024;
    float s = 0.f;
    for (int i = tid; i < 1024; i += 256) s += h[i] * g_wq[i & 31];
    __shared__ float red[8];
    for (int o = 16; o > 0; o >>= 1) s += __shfl_down_sync(0xffffffffu, s, o);
    if ((tid & 31) == 0) red[tid >> 5] = s;
    __syncthreads();
    if (tid == 0) {
        float tot = 0.f;
        for (int w = 0; w < 8; w++) tot += red[w];
        int c = bc & 63;
        float sw = 0.f;
        for (int g = 0; g < 32; g++) sw += Wg[c * 32 + g];
        g_ftmax[bc] = tot * sw;
    }
}

// ---------------- B[b,d] = b1[d] + sum_c W1[d, 64+c] * ftmax[b,c] ---------------
__global__ void k_bvec(const float* __restrict__ W1, const float* __restrict__ b1) {
    int i = threadIdx.x;                  // 512
    int b = i >> 6, d = i & 63;
    float s = b1[d];
    for (int c = 0; c < 64; c++) s += W1[d * 128 + 64 + c] * g_ftmax[b * 64 + c];
    g_Bvec[i] = s;
}

// ---------------- fused head, FFMA2, relu in place ------------------------------
__global__ void __launch_bounds__(256, 2) k_main(
    const float* __restrict__ W1, const float* __restrict__ Wg,
    const float* __restrict__ W2, const float* __restrict__ b2,
    float* __restrict__ out) {
    __shared__ __align__(16) float s_w1t[64 * 68];  // [c][d], pad 68
    __shared__ __align__(16) float s_w2t[64 * 36];  // [d][e], pad 36
    __shared__ float s_wg[64 * 32];                 // [c][g]
    __shared__ float s_h[64 * 32];                  // [c][p]
    __shared__ float s_B[64];
    __shared__ float s_b2[32];

    const int tid = threadIdx.x;
    const int w = tid >> 5, lane = tid & 31;
    const int b = blockIdx.y;
    const int pos0 = blockIdx.x * 32;

    for (int i = tid; i < 4096; i += 256) {
        int d = i >> 6, c = i & 63;
        s_w1t[c * 68 + d] = W1[d * 128 + c];
    }
    for (int i = tid; i < 2048; i += 256) {
        int e = i >> 6, d = i & 63;
        s_w2t[d * 36 + e] = W2[i];
    }
    for (int i = tid; i < 2048; i += 256) s_wg[i] = Wg[i];
    for (int i = tid; i < 2048; i += 256) {
        int c = i >> 5, p = i & 31;
        s_h[i] = g_h2[(b * 64 + c) * 1024 + pos0 + p];
    }
    if (tid < 64) s_B[tid] = g_Bvec[b * 64 + tid];
    if (tid < 32) s_b2[tid] = b2[tid];
    __syncthreads();

    for (int r = 0; r < 4; r++) {
        const int p = r * 8 + w;            // this warp's position (0..31)
        // ---- GEMM1: P[d (all 64)][g=lane] ----
        unsigned long long acc[32];
        #pragma unroll
        for (int i = 0; i < 32; i++) acc[i] = 0ull;
        #pragma unroll 2
        for (int c = 0; c < 64; c++) {
            float uv = s_wg[c * 32 + lane] * s_h[c * 32 + p];
            unsigned long long uvd = pack2(uv, uv);
            const ulonglong2* wrow = (const ulonglong2*)&s_w1t[c * 68];
            #pragma unroll
            for (int i = 0; i < 16; i++) {
                ulonglong2 v = wrow[i];
                acc[2 * i]     = ffma2(v.x, uvd, acc[2 * i]);
                acc[2 * i + 1] = ffma2(v.y, uvd, acc[2 * i + 1]);
            }
        }
        // ---- relu(P + B) in place ----
        #pragma unroll
        for (int i = 0; i < 32; i++) {
            float lo, hi;
            unpack2(acc[i], lo, hi);
            lo = fmaxf(lo + s_B[2 * i], 0.f);
            hi = fmaxf(hi + s_B[2 * i + 1], 0.f);
            acc[i] = pack2(lo, hi);
        }
        // ---- GEMM2: out[e (32)][g=lane] ----
        unsigned long long acc2[16];
        #pragma unroll
        for (int i = 0; i < 16; i++) acc2[i] = 0ull;
        #pragma unroll 2
        for (int i = 0; i < 32; i++) {
            float lo, hi;
            unpack2(acc[i], lo, hi);
            unsigned long long sd0 = pack2(lo, lo);
            unsigned long long sd1 = pack2(hi, hi);
            const ulonglong2* w2r0 = (const ulonglong2*)&s_w2t[(2 * i) * 36];
            const ulonglong2* w2r1 = (const ulonglong2*)&s_w2t[(2 * i + 1) * 36];
            #pragma unroll
            for (int j = 0; j < 8; j++) {
                ulonglong2 v0 = w2r0[j];
                acc2[2 * j]     = ffma2(v0.x, sd0, acc2[2 * j]);
                acc2[2 * j + 1] = ffma2(v0.y, sd0, acc2[2 * j + 1]);
            }
            #pragma unroll
            for (int j = 0; j < 8; j++) {
                ulonglong2 v1 = w2r1[j];
                acc2[2 * j]     = ffma2(v1.x, sd1, acc2[2 * j]);
                acc2[2 * j + 1] = ffma2(v1.y, sd1, acc2[2 * j + 1]);
            }
        }
        // ---- epilogue: +b2, store (coalesced over g=lane) ----
        const int pos = pos0 + p;
        float* op = out + ((size_t)(b * 32) * 1024 + pos) * 32 + lane;
        #pragma unroll
        for (int j = 0; j < 16; j++) {
            float lo, hi;
            unpack2(acc2[j], lo, hi);
            lo += s_b2[2 * j];
            hi += s_b2[2 * j + 1];
            op[(size_t)(2 * j) * 32768]     = lo;
            op[(size_t)(2 * j + 1) * 32768] = hi;
        }
    }
}

// ---------------- ft_g: per (b,e) max over contiguous 32768 values ---------------
__global__ void k_ftg(const float* __restrict__ outv, float* __restrict__ tail) {
    int bc = blockIdx.x;                   // 256
    int tid = threadIdx.x;                 // 256
    const float4* p = (const float4*)(outv + (size_t)bc * 32768);
    float m = -3.4e38f;
    for (int i = tid; i < 8192; i += 256) {
        float4 v = p[i];
        m = fmaxf(m, fmaxf(fmaxf(v.x, v.y), fmaxf(v.z, v.w)));
    }
    __shared__ float red[8];
    for (int o = 16; o > 0; o >>= 1) m = fmaxf(m, __shfl_xor_sync(0xffffffffu, m, o));
    if ((tid & 31) == 0) red[tid >> 5] = m;
    __syncthreads();
    if (tid == 0) {
        for (int i = 1; i < 8; i++) m = fmaxf(m, red[i]);
        tail[bc] = m;
    }
}

// ---------------- launch --------------------------------------------------------
extern "C" void kernel_launch(void* const* d_in, const int* in_sizes, int n_in,
                              void* d_out, int out_size) {
    const float* pts   = (const float*)d_in[0];
    const float* scale = (const float*)d_in[1];
    const float* sigma = (const float*)d_in[2];
    const float* A     = (const float*)d_in[3];
    const float* icmp  = (const float*)d_in[4];
    int base = (n_in >= 16) ? 7 : 5;     // skip res_pt/res_r int scalars if present
    const float* Ws1 = (const float*)d_in[base + 0];
    const float* bs1 = (const float*)d_in[base + 1];
    const float* Ws2 = (const float*)d_in[base + 2];
    const float* bs2 = (const float*)d_in[base + 3];
    const float* Wg  = (const float*)d_in[base + 4];
    const float* W1  = (const float*)d_in[base + 5];
    const float* b1  = (const float*)d_in[base + 6];
    const float* W2  = (const float*)d_in[base + 7];
    const float* b2  = (const float*)d_in[base + 8];
    float* out = (float*)d_out;

    float *ftp = nullptr, *h1p = nullptr, *h2p = nullptr;
    cudaGetSymbolAddress((void**)&ftp, g_ft);
    cudaGetSymbolAddress((void**)&h1p, g_h1);
    cudaGetSymbolAddress((void**)&h2p, g_h2);

    k_init<<<256, 256>>>();
    k_scatter<<<(NB * NPT + 255) / 256, 256>>>(pts, scale, sigma, A, icmp);
    k_conv<8, 1, 8, 32><<<dim3(16, 1, 8), 256>>>(ftp, Ws1, bs1, h1p);
    k_conv<16, 2, 32, 64><<<dim3(16, 2, 8), 256>>>(h1p, Ws2, bs2, h2p);
    k_ftmax<<<512, 256>>>(Wg);
    k_bvec<<<1, 512>>>(W1, b1);
    k_main<<<dim3(32, NB), 256>>>(W1, Wg, W2, b2, out);
    k_ftg<<<256, 256>>>(out, out + (size_t)NB * 32 * 1024 * 32);
}

// round 5
// speedup vs baseline: 1.0095x; 1.0095x over previous
#include <cuda_runtime.h>
#include <math.h>

#define RP 32
#define RR 8
#define NB 8
#define NPT 32768
#define PI_F 3.14159265358979323846f

// ---------------- scratch (device globals; no allocation allowed) ----------------
__device__ float g_ft[NB * RR * RP * RP];     // (b, r, theta, phi)
__device__ float g_h1[NB * 32 * RP * RP];     // conv1 out
__device__ float g_h2[NB * 64 * RP * RP];     // conv2 out
__device__ float g_ftmax[NB * 64];
__device__ float g_Bvec[NB * 64];
__device__ float g_wq[RP];

// ---------------- f32x2 packed helpers ------------------------------------------
__device__ __forceinline__ unsigned long long ffma2(unsigned long long a,
                                                    unsigned long long b,
                                                    unsigned long long c) {
    unsigned long long d;
    asm("fma.rn.f32x2 %0, %1, %2, %3;" : "=l"(d) : "l"(a), "l"(b), "l"(c));
    return d;
}
__device__ __forceinline__ unsigned long long pack2(float lo, float hi) {
    unsigned long long d;
    asm("mov.b64 %0, {%1, %2};" : "=l"(d) : "f"(lo), "f"(hi));
    return d;
}
__device__ __forceinline__ void unpack2(unsigned long long v, float& lo, float& hi) {
    asm("mov.b64 {%0, %1}, %2;" : "=f"(lo), "=f"(hi) : "l"(v));
}

// ---------------- init: zero grid + quadrature weights --------------------------
__global__ void k_init() {
    int i = blockIdx.x * blockDim.x + threadIdx.x;   // 65536 threads
    g_ft[i] = 0.f;                                   // exactly covers 65536
    if (i < RP) {
        // Driscoll-Healy weights, bw = 16
        double jj = (double)i;
        double theta = M_PI * (2.0 * jj + 1.0) / 64.0;
        double s = 0.0;
        for (int k = 0; k < 16; k++)
            s += sin((2.0 * jj + 1.0) * (2.0 * k + 1.0) * M_PI / 64.0) / (2.0 * k + 1.0);
        g_wq[i] = (float)((2.0 / 16.0) * sin(theta) * s);
    }
}

// ---------------- scatter: gaussian splat of w into (b, r, t, p) grid ------------
__global__ void __launch_bounds__(256) k_scatter(const float* __restrict__ pts,
                          const float* __restrict__ scp, const float* __restrict__ sgp,
                          const float* __restrict__ Ap, const float* __restrict__ icp) {
    int i = blockIdx.x * blockDim.x + threadIdx.x;
    if (i >= NB * NPT) return;
    float scale = *scp, sigma = *sgp, A = *Ap, icc = *icp;
    float x = pts[i * 3 + 0], y = pts[i * 3 + 1], z = pts[i * 3 + 2];
    float r = fmaxf(sqrtf(x * x + y * y + z * z), 0.1f);
    float th = acosf(fminf(fmaxf(__fdividef(z, r), -1.f), 1.f));
    float ph = atan2f(y, x) + PI_F;
    float ct = th * (float)(RP / M_PI);
    float cp = ph * (float)(RP / (2.0 * M_PI));
    float cr = __fdividef(r, scale) * (float)RR;
    int it = min(max((int)floorf(ct), 0), RP - 1);
    int ip = min(max((int)floorf(cp), 0), RP - 1);
    int ir = min(max((int)floorf(cr), 0), RR - 1);
    float dt = ct - ((float)it + icc);
    float dp = cp - ((float)ip + icc);
    float dr = cr - ((float)ir + icc);
    float d2 = dt * dt + dp * dp + dr * dr;
    float w = A * __expf(-d2 * __fdividef(0.5f, sigma * sigma));
    int b = i >> 15;
    atomicAdd(&g_ft[((b * RR + ir) * RP + it) * RP + ip], w);
}

// ---------------- register-tiled 3x3 SAME conv + relu, 2-row tiles --------------
// block: 256 threads = (ocq: tid>>5 -> 8 quads of 4 oc, row: (tid>>4)&1, colq: tid&15 -> 2 cols)
// covers 32 oc x 2 rows x 32 cols. grid: (16 rowtiles, OCT/32, 8 b).
template<int ICP, int PHASES, int ICT, int OCT>
__global__ void __launch_bounds__(256) k_conv(const float* __restrict__ in,
                                              const float* __restrict__ W,
                                              const float* __restrict__ bias,
                                              float* __restrict__ outp) {
    __shared__ __align__(16) float s_in[ICP * 4 * 36];
    __shared__ __align__(16) float s_w[ICP * 9 * 32];
    const int tid = threadIdx.x;
    const int rt = blockIdx.x;
    const int ocg = blockIdx.y;
    const int b = blockIdx.z;
    const int r0 = rt * 2;
    const int colq = tid & 15;           // 16 quads of 2 cols
    const int row = (tid >> 4) & 1;      // 2 rows
    const int ocq = tid >> 5;            // 8 quads of 4 oc

    float acc[4][2];
    #pragma unroll
    for (int a = 0; a < 4; a++) {
        float bb = bias[ocg * 32 + ocq * 4 + a];
        acc[a][0] = bb; acc[a][1] = bb;
    }

    for (int ph = 0; ph < PHASES; ph++) {
        const int icb = ph * ICP;
        __syncthreads();
        for (int i = tid; i < ICP * 144; i += 256) {
            int ic = i / 144, rem = i % 144;
            int rr = rem / 36, cc = rem % 36;
            int X = r0 + rr - 1, Y = cc - 1;
            float v = 0.f;
            if (X >= 0 && X < 32 && Y >= 0 && Y < 32)
                v = in[((b * ICT + icb + ic) * 32 + X) * 32 + Y];
            s_in[i] = v;
        }
        for (int i = tid; i < ICP * 288; i += 256) {
            int ic = i / 288, rem = i % 288;
            int k9 = rem >> 5, oc = rem & 31;
            s_w[i] = W[(ocg * 32 + oc) * (ICT * 9) + (icb + ic) * 9 + k9];
        }
        __syncthreads();
        #pragma unroll 1
        for (int ic = 0; ic < ICP; ic++) {
            #pragma unroll
            for (int dy = 0; dy < 3; dy++) {
                const float* irow = &s_in[(ic * 4 + row + dy) * 36 + colq * 2];
                float2 f01 = *(const float2*)irow;
                float2 f23 = *(const float2*)(irow + 2);
                float f[4] = {f01.x, f01.y, f23.x, f23.y};
                const float* wr = &s_w[(ic * 3 + dy) * 96 + ocq * 4];
                float4 w0 = *(const float4*)(wr);
                float4 w1 = *(const float4*)(wr + 32);
                float4 w2 = *(const float4*)(wr + 64);
                #pragma unroll
                for (int k = 0; k < 2; k++) {
                    acc[0][k] += f[k] * w0.x;     acc[1][k] += f[k] * w0.y;
                    acc[2][k] += f[k] * w0.z;     acc[3][k] += f[k] * w0.w;
                    acc[0][k] += f[k + 1] * w1.x; acc[1][k] += f[k + 1] * w1.y;
                    acc[2][k] += f[k + 1] * w1.z; acc[3][k] += f[k + 1] * w1.w;
                    acc[0][k] += f[k + 2] * w2.x; acc[1][k] += f[k + 2] * w2.y;
                    acc[2][k] += f[k + 2] * w2.z; acc[3][k] += f[k + 2] * w2.w;
                }
            }
        }
    }
    #pragma unroll
    for (int a = 0; a < 4; a++) {
        float2 vv = make_float2(fmaxf(acc[a][0], 0.f), fmaxf(acc[a][1], 0.f));
        *(float2*)&outp[((b * OCT + ocg * 32 + ocq * 4 + a) * 32 + r0 + row) * 32 + colq * 2] = vv;
    }
}

// ---------------- ft_max[b,c] = (sum_xy h * wq[y]) * sum_g Wg[c,g] --------------
__global__ void k_ftmax(const float* __restrict__ Wg) {
    int bc = blockIdx.x;                  // 512
    int tid = threadIdx.x;                // 256
    const float* h = g_h2 + bc * 1024;
    float s = 0.f;
    for (int i = tid; i < 1024; i += 256) s += h[i] * g_wq[i & 31];
    __shared__ float red[8];
    for (int o = 16; o > 0; o >>= 1) s += __shfl_down_sync(0xffffffffu, s, o);
    if ((tid & 31) == 0) red[tid >> 5] = s;
    __syncthreads();
    if (tid == 0) {
        float tot = 0.f;
        for (int w = 0; w < 8; w++) tot += red[w];
        int c = bc & 63;
        float sw = 0.f;
        for (int g = 0; g < 32; g++) sw += Wg[c * 32 + g];
        g_ftmax[bc] = tot * sw;
    }
}

// ---------------- B[b,d] = b1[d] + sum_c W1[d, 64+c] * ftmax[b,c] ---------------
__global__ void k_bvec(const float* __restrict__ W1, const float* __restrict__ b1) {
    int i = threadIdx.x;                  // 512
    int b = i >> 6, d = i & 63;
    float s = b1[d];
    for (int c = 0; c < 64; c++) s += W1[d * 128 + 64 + c] * g_ftmax[b * 64 + c];
    g_Bvec[i] = s;
}

// ---------------- fused head, FFMA2, relu in place ------------------------------
__global__ void __launch_bounds__(256, 2) k_main(
    const float* __restrict__ W1, const float* __restrict__ Wg,
    const float* __restrict__ W2, const float* __restrict__ b2,
    float* __restrict__ out) {
    __shared__ __align__(16) float s_w1t[64 * 68];  // [c][d], pad 68
    __shared__ __align__(16) float s_w2t[64 * 36];  // [d][e], pad 36
    __shared__ float s_wg[64 * 32];                 // [c][g]
    __shared__ float s_h[64 * 32];                  // [c][p]
    __shared__ float s_B[64];
    __shared__ float s_b2[32];

    const int tid = threadIdx.x;
    const int w = tid >> 5, lane = tid & 31;
    const int b = blockIdx.y;
    const int pos0 = blockIdx.x * 32;

    for (int i = tid; i < 4096; i += 256) {
        int d = i >> 6, c = i & 63;
        s_w1t[c * 68 + d] = W1[d * 128 + c];
    }
    for (int i = tid; i < 2048; i += 256) {
        int e = i >> 6, d = i & 63;
        s_w2t[d * 36 + e] = W2[i];
    }
    for (int i = tid; i < 2048; i += 256) s_wg[i] = Wg[i];
    for (int i = tid; i < 2048; i += 256) {
        int c = i >> 5, p = i & 31;
        s_h[i] = g_h2[(b * 64 + c) * 1024 + pos0 + p];
    }
    if (tid < 64) s_B[tid] = g_Bvec[b * 64 + tid];
    if (tid < 32) s_b2[tid] = b2[tid];
    __syncthreads();

    for (int r = 0; r < 4; r++) {
        const int p = r * 8 + w;            // this warp's position (0..31)
        // ---- GEMM1: P[d (all 64)][g=lane] ----
        unsigned long long acc[32];
        #pragma unroll
        for (int i = 0; i < 32; i++) acc[i] = 0ull;
        #pragma unroll 2
        for (int c = 0; c < 64; c++) {
            float uv = s_wg[c * 32 + lane] * s_h[c * 32 + p];
            unsigned long long uvd = pack2(uv, uv);
            const ulonglong2* wrow = (const ulonglong2*)&s_w1t[c * 68];
            #pragma unroll
            for (int i = 0; i < 16; i++) {
                ulonglong2 v = wrow[i];
                acc[2 * i]     = ffma2(v.x, uvd, acc[2 * i]);
                acc[2 * i + 1] = ffma2(v.y, uvd, acc[2 * i + 1]);
            }
        }
        // ---- relu(P + B) in place ----
        #pragma unroll
        for (int i = 0; i < 32; i++) {
            float lo, hi;
            unpack2(acc[i], lo, hi);
            lo = fmaxf(lo + s_B[2 * i], 0.f);
            hi = fmaxf(hi + s_B[2 * i + 1], 0.f);
            acc[i] = pack2(lo, hi);
        }
        // ---- GEMM2: out[e (32)][g=lane] ----
        unsigned long long acc2[16];
        #pragma unroll
        for (int i = 0; i < 16; i++) acc2[i] = 0ull;
        #pragma unroll 2
        for (int i = 0; i < 32; i++) {
            float lo, hi;
            unpack2(acc[i], lo, hi);
            unsigned long long sd0 = pack2(lo, lo);
            unsigned long long sd1 = pack2(hi, hi);
            const ulonglong2* w2r0 = (const ulonglong2*)&s_w2t[(2 * i) * 36];
            const ulonglong2* w2r1 = (const ulonglong2*)&s_w2t[(2 * i + 1) * 36];
            #pragma unroll
            for (int j = 0; j < 8; j++) {
                ulonglong2 v0 = w2r0[j];
                acc2[2 * j]     = ffma2(v0.x, sd0, acc2[2 * j]);
                acc2[2 * j + 1] = ffma2(v0.y, sd0, acc2[2 * j + 1]);
            }
            #pragma unroll
            for (int j = 0; j < 8; j++) {
                ulonglong2 v1 = w2r1[j];
                acc2[2 * j]     = ffma2(v1.x, sd1, acc2[2 * j]);
                acc2[2 * j + 1] = ffma2(v1.y, sd1, acc2[2 * j + 1]);
            }
        }
        // ---- epilogue: +b2, store (coalesced over g=lane) ----
        const int pos = pos0 + p;
        float* op = out + ((size_t)(b * 32) * 1024 + pos) * 32 + lane;
        #pragma unroll
        for (int j = 0; j < 16; j++) {
            float lo, hi;
            unpack2(acc2[j], lo, hi);
            lo += s_b2[2 * j];
            hi += s_b2[2 * j + 1];
            op[(size_t)(2 * j) * 32768]     = lo;
            op[(size_t)(2 * j + 1) * 32768] = hi;
        }
    }
}

// ---------------- ft_g: per (b,e) max over contiguous 32768 values ---------------
__global__ void k_ftg(const float* __restrict__ outv, float* __restrict__ tail) {
    int bc = blockIdx.x;                   // 256
    int tid = threadIdx.x;                 // 256
    const float4* p = (const float4*)(outv + (size_t)bc * 32768);
    float m = -3.4e38f;
    for (int i = tid; i < 8192; i += 256) {
        float4 v = p[i];
        m = fmaxf(m, fmaxf(fmaxf(v.x, v.y), fmaxf(v.z, v.w)));
    }
    __shared__ float red[8];
    for (int o = 16; o > 0; o >>= 1) m = fmaxf(m, __shfl_xor_sync(0xffffffffu, m, o));
    if ((tid & 31) == 0) red[tid >> 5] = m;
    __syncthreads();
    if (tid == 0) {
        for (int i = 1; i < 8; i++) m = fmaxf(m, red[i]);
        tail[bc] = m;
    }
}

// ---------------- launch --------------------------------------------------------
extern "C" void kernel_launch(void* const* d_in, const int* in_sizes, int n_in,
                              void* d_out, int out_size) {
    const float* pts   = (const float*)d_in[0];
    const float* scale = (const float*)d_in[1];
    const float* sigma = (const float*)d_in[2];
    const float* A     = (const float*)d_in[3];
    const float* icmp  = (const float*)d_in[4];
    int base = (n_in >= 16) ? 7 : 5;     // skip res_pt/res_r int scalars if present
    const float* Ws1 = (const float*)d_in[base + 0];
    const float* bs1 = (const float*)d_in[base + 1];
    const float* Ws2 = (const float*)d_in[base + 2];
    const float* bs2 = (const float*)d_in[base + 3];
    const float* Wg  = (const float*)d_in[base + 4];
    const float* W1  = (const float*)d_in[base + 5];
    const float* b1  = (const float*)d_in[base + 6];
    const float* W2  = (const float*)d_in[base + 7];
    const float* b2  = (const float*)d_in[base + 8];
    float* out = (float*)d_out;

    float *ftp = nullptr, *h1p = nullptr, *h2p = nullptr;
    cudaGetSymbolAddress((void**)&ftp, g_ft);
    cudaGetSymbolAddress((void**)&h1p, g_h1);
    cudaGetSymbolAddress((void**)&h2p, g_h2);

    k_init<<<256, 256>>>();
    k_scatter<<<(NB * NPT + 255) / 256, 256>>>(pts, scale, sigma, A, icmp);
    k_conv<8, 1, 8, 32><<<dim3(16, 1, 8), 256>>>(ftp, Ws1, bs1, h1p);
    k_conv<16, 2, 32, 64><<<dim3(16, 2, 8), 256>>>(h1p, Ws2, bs2, h2p);
    k_ftmax<<<512, 256>>>(Wg);
    k_bvec<<<1, 512>>>(W1, b1);
    k_main<<<dim3(32, NB), 256>>>(W1, Wg, W2, b2, out);
    k_ftg<<<256, 256>>>(out, out + (size_t)NB * 32 * 1024 * 32);
}